// round 1
// baseline (speedup 1.0000x reference)
#include <cuda_runtime.h>

// Problem constants
#define Bn 8
#define Cn 64
#define Hn 256
#define Wn 256
#define NGROUPS 8
#define NPG 524288           // elements per (b, group) = 8*256*256
#define NTOT 33554432        // B*C*H*W

// ---------------- device scratch (static allocation only) ----------------
static __device__ double d_gsum[64];
static __device__ double d_gsumsq[64];
static __device__ float  d_mu[64];
static __device__ float  d_rstd[64];
static __device__ float  d_weff[8 * 8192];    // [b][k][o], o<64 gate, o>=64 upd
static __device__ float  d_biaseff[8 * 128];
static __device__ float  d_gate[NTOT];        // sigmoid(gate logits)
static __device__ float  d_hw[NTOT];          // column-scan result

// ---------------- f32x2 packed FMA helpers (Blackwell FFMA2 path) --------
__device__ __forceinline__ unsigned long long fma2(unsigned long long a,
                                                   unsigned long long b,
                                                   unsigned long long c) {
    unsigned long long d;
    asm("fma.rn.f32x2 %0, %1, %2, %3;" : "=l"(d) : "l"(a), "l"(b), "l"(c));
    return d;
}
__device__ __forceinline__ unsigned long long pack2(float lo, float hi) {
    unsigned long long d;
    asm("mov.b64 %0, {%1, %2};" : "=l"(d) : "f"(lo), "f"(hi));
    return d;
}
__device__ __forceinline__ void unpack2(unsigned long long v, float& lo, float& hi) {
    asm("mov.b64 {%0, %1}, %2;" : "=f"(lo), "=f"(hi) : "l"(v));
}
__device__ __forceinline__ float sigmoidf_fast(float z) {
    return __fdividef(1.0f, 1.0f + __expf(-z));
}

// ---------------- K0: zero GN accumulators (graph replays need this) -----
__global__ void k_zero() {
    int t = threadIdx.x;
    if (t < 64) { d_gsum[t] = 0.0; d_gsumsq[t] = 0.0; }
}

// ---------------- K1: GN partial stats -----------------------------------
// grid 1024 = 64 (b,g) groups x 16 slices; each (b,g) region is contiguous.
__global__ __launch_bounds__(256) void k_gn_stats(const float* __restrict__ x) {
    const int grp   = blockIdx.x >> 4;
    const int slice = blockIdx.x & 15;
    const float4* p = (const float4*)x + (size_t)grp * 131072 + slice * 8192;
    float s = 0.f, ss = 0.f;
#pragma unroll 4
    for (int i = threadIdx.x; i < 8192; i += 256) {
        float4 v = p[i];
        s  += (v.x + v.y) + (v.z + v.w);
        ss += (v.x * v.x + v.y * v.y) + (v.z * v.z + v.w * v.w);
    }
    for (int off = 16; off; off >>= 1) {
        s  += __shfl_down_sync(0xffffffffu, s,  off);
        ss += __shfl_down_sync(0xffffffffu, ss, off);
    }
    __shared__ float rs[8], rss[8];
    int w = threadIdx.x >> 5, l = threadIdx.x & 31;
    if (l == 0) { rs[w] = s; rss[w] = ss; }
    __syncthreads();
    if (threadIdx.x == 0) {
        double S = 0.0, SS = 0.0;
#pragma unroll
        for (int i = 0; i < 8; i++) { S += (double)rs[i]; SS += (double)rss[i]; }
        atomicAdd(&d_gsum[grp], S);
        atomicAdd(&d_gsumsq[grp], SS);
    }
}

// ---------------- K2a: finalize mu / rstd --------------------------------
__global__ void k_gn_finalize() {
    int t = threadIdx.x;
    if (t < 64) {
        const double n = (double)NPG;
        double mu  = d_gsum[t] / n;
        double var = d_gsumsq[t] / n - mu * mu;
        d_mu[t]   = (float)mu;
        d_rstd[t] = (float)(1.0 / sqrt(var + 1e-5));
    }
}

// ---------------- K2b: fold GN affine into per-batch weights -------------
__global__ __launch_bounds__(256) void k_weff(const float* __restrict__ gw,
                                              const float* __restrict__ gb,
                                              const float* __restrict__ uw,
                                              const float* __restrict__ ub,
                                              const float* __restrict__ gnw,
                                              const float* __restrict__ gnb) {
    const int b = blockIdx.x;
    for (int idx = threadIdx.x; idx < 8192; idx += 256) {
        int k = idx >> 7, o = idx & 127;
        float w = (o < 64) ? gw[o * 64 + k] : uw[(o - 64) * 64 + k];
        d_weff[b * 8192 + idx] = w * gnw[k] * d_rstd[b * 8 + (k >> 3)];
    }
    if (threadIdx.x < 128) {
        int o = threadIdx.x;
        float acc = (o < 64) ? gb[o] : ub[o - 64];
        for (int k = 0; k < 64; k++) {
            float w = (o < 64) ? gw[o * 64 + k] : uw[(o - 64) * 64 + k];
            int g = b * 8 + (k >> 3);
            acc += w * (gnb[k] - d_mu[g] * d_rstd[g] * gnw[k]);
        }
        d_biaseff[b * 128 + o] = acc;
    }
}

// ---------------- K3: fused 1x1 convs + column scan over W ---------------
// One block per (b, h) row. 2048 blocks x 256 threads. Static SMEM = 47 KB.
__global__ __launch_bounds__(256) void k_colscan(const float* __restrict__ x) {
    __shared__ float Wsm[8192];       // [k][o] (o: 0..63 gate, 64..127 upd)
    __shared__ float bsm[128];
    __shared__ float hv[64 * 20];     // raw x chunk [c][16], pad 20 (16B-aligned rows)
    __shared__ float gsm[64 * 17];    // sigmoid(gate) chunk, pad 17 (conflict-free)
    __shared__ float usm[64 * 17];    // u chunk, then overwritten with hw

    const int t = threadIdx.x;
    const int b = blockIdx.x >> 8;
    const int h = blockIdx.x & 255;

#pragma unroll 4
    for (int i = t; i < 8192; i += 256) Wsm[i] = d_weff[b * 8192 + i];
    if (t < 128) bsm[t] = d_biaseff[b * 128 + t];
    __syncthreads();

    const int o  = t & 127;           // output channel (gate or upd)
    const int wq = t >> 7;            // 0..1, 8 w positions each
    const int cl = t >> 2;            // load: channel
    const int fl = t & 3;             // load: float4 index within chunk

    const float* xrow = x + (((size_t)b * 64 + cl) * 256 + h) * 256;
    const bool is_gate = (o < 64);
    float* stg = is_gate ? &gsm[o * 17 + wq * 8] : &usm[(o - 64) * 17 + wq * 8];
    const float bb = bsm[o];
    float s_carry = 0.f;

    for (int ch = 0; ch < 16; ch++) {
        const int w0 = ch * 16;
        // ---- Phase A: coalesced load of x chunk into SMEM ----
        {
            float4 v = *(const float4*)(xrow + w0 + fl * 4);
            *(float4*)&hv[cl * 20 + fl * 4] = v;
        }
        __syncthreads();
        // ---- Phase B: 128x64 matvec for 16 pixels via FFMA2 ----
        {
            unsigned long long a0 = 0, a1 = 0, a2 = 0, a3 = 0;
#pragma unroll 16
            for (int k = 0; k < 64; k++) {
                float wv = Wsm[k * 128 + o];
                unsigned long long wv2 = pack2(wv, wv);
                const ulonglong2* hp = (const ulonglong2*)&hv[k * 20 + wq * 8];
                ulonglong2 hA = hp[0];
                ulonglong2 hB = hp[1];
                a0 = fma2(wv2, hA.x, a0);
                a1 = fma2(wv2, hA.y, a1);
                a2 = fma2(wv2, hB.x, a2);
                a3 = fma2(wv2, hB.y, a3);
            }
            float r0, r1, r2, r3, r4, r5, r6, r7;
            unpack2(a0, r0, r1); unpack2(a1, r2, r3);
            unpack2(a2, r4, r5); unpack2(a3, r6, r7);
            r0 += bb; r1 += bb; r2 += bb; r3 += bb;
            r4 += bb; r5 += bb; r6 += bb; r7 += bb;
            if (is_gate) {
                stg[0] = sigmoidf_fast(r0); stg[1] = sigmoidf_fast(r1);
                stg[2] = sigmoidf_fast(r2); stg[3] = sigmoidf_fast(r3);
                stg[4] = sigmoidf_fast(r4); stg[5] = sigmoidf_fast(r5);
                stg[6] = sigmoidf_fast(r6); stg[7] = sigmoidf_fast(r7);
            } else {
                stg[0] = r0; stg[1] = r1; stg[2] = r2; stg[3] = r3;
                stg[4] = r4; stg[5] = r5; stg[6] = r6; stg[7] = r7;
            }
        }
        __syncthreads();
        // ---- Phase C: sequential gated scan along w (64 threads) ----
        if (t < 64) {
            float s = s_carry;
#pragma unroll
            for (int j = 0; j < 16; j++) {
                float g = gsm[t * 17 + j];
                float u = usm[t * 17 + j];
                s = fmaf(g, s, fmaf(-g, u, u));   // g*s + (1-g)*u
                usm[t * 17 + j] = s;              // overwrite u with hw
            }
            s_carry = s;
        }
        __syncthreads();
        // ---- Phase D: coalesced writeback of gate + hw ----
#pragma unroll
        for (int idx = t; idx < 1024; idx += 256) {
            int c = idx >> 4, j = idx & 15;
            int gi = (((b * 64 + c) * 256 + h) * 256) + w0 + j;
            d_gate[gi] = gsm[c * 17 + j];
            d_hw[gi]   = usm[c * 17 + j];
        }
        // no sync needed: next Phase A only writes hv (not read in C/D),
        // and the post-A barrier orders D-reads before next B-writes.
    }
}

// ---------------- K4: row scan over H + residual add ---------------------
// 131072 threads: one per (b, c, w). Fully coalesced at every h-step.
__global__ __launch_bounds__(256) void k_rowscan(const float* __restrict__ x,
                                                 float* __restrict__ out) {
    const int idx  = blockIdx.x * 256 + threadIdx.x;     // 0..131071
    const int base = (idx >> 8) * 65536 + (idx & 255);   // (b*64+c)*H*W + w
    float s = 0.f;
#pragma unroll 8
    for (int h = 0; h < 256; h++) {
        int p = base + (h << 8);
        float g  = d_gate[p];
        float u  = d_hw[p];
        float xv = x[p];
        s = fmaf(g, s, fmaf(-g, u, u));
        out[p] = xv + s;
    }
}

// ---------------- launch --------------------------------------------------
extern "C" void kernel_launch(void* const* d_in, const int* in_sizes, int n_in,
                              void* d_out, int out_size) {
    const float* x      = (const float*)d_in[0];
    const float* gn_w   = (const float*)d_in[1];
    const float* gn_b   = (const float*)d_in[2];
    const float* gate_w = (const float*)d_in[3];
    const float* gate_b = (const float*)d_in[4];
    const float* upd_w  = (const float*)d_in[5];
    const float* upd_b  = (const float*)d_in[6];
    float* out = (float*)d_out;

    k_zero<<<1, 64>>>();
    k_gn_stats<<<1024, 256>>>(x);
    k_gn_finalize<<<1, 64>>>();
    k_weff<<<8, 256>>>(gate_w, gate_b, upd_w, upd_b, gn_w, gn_b);
    k_colscan<<<2048, 256>>>(x);
    k_rowscan<<<512, 256>>>(x, out);
}